// round 16
// baseline (speedup 1.0000x reference)
#include <cuda_runtime.h>
#include <cuda_bf16.h>
#include <math.h>
#include <stdint.h>

#define NND 100000
#define D 128
#define NELEM (NND*D)
#define EMAX 2000000
#define NBLK 98           // ceil(100000/1024)
#define NTILES 391        // ceil(100000/256)
#define NND_PAD (NTILES*256)   // 100096
#define GEMM_GRID 148

// Scratch (allocation-free)
__device__ float  g_buf0[NELEM];
__device__ float  g_buf1[NELEM];
__device__ double g_sum[3];
__device__ double g_sumsq[3];
__device__ int    g_deg[NND + 1];
__device__ int    g_off[NND + 1];
__device__ int    g_cursor[NND];
__device__ int    g_srcs[EMAX];
__device__ int    g_blocksum[128];
__device__ int    g_blockoff[128];
// h = GIN-aggregated features, pre-split to bf16 hi/lo (padded to tile grid).
__device__ __nv_bfloat16 g_hhi[NND_PAD * D];
__device__ __nv_bfloat16 g_hlo[NND_PAD * D];
// bf16 hi/lo images of the three weight matrices, [k][n] row-major.
__device__ __nv_bfloat16 g_wimg[3][2][16384];

__device__ __forceinline__ uint32_t smem_u32(const void* p) {
    uint32_t a;
    asm("{ .reg .u64 t; cvta.to.shared.u64 t, %1; cvt.u32.u64 %0, t; }" : "=r"(a) : "l"(p));
    return a;
}

__device__ __forceinline__ void ldsm_x4(uint32_t* r, uint32_t addr) {
    asm volatile("ldmatrix.sync.aligned.m8n8.x4.shared.b16 {%0,%1,%2,%3}, [%4];"
                 : "=r"(r[0]), "=r"(r[1]), "=r"(r[2]), "=r"(r[3]) : "r"(addr));
}
__device__ __forceinline__ void ldsm_x4_t(uint32_t* r, uint32_t addr) {
    asm volatile("ldmatrix.sync.aligned.m8n8.x4.trans.shared.b16 {%0,%1,%2,%3}, [%4];"
                 : "=r"(r[0]), "=r"(r[1]), "=r"(r[2]), "=r"(r[3]) : "r"(addr));
}
__device__ __forceinline__ void mma_bf16(float* d, const uint32_t* a, const uint32_t* b) {
    asm volatile(
        "mma.sync.aligned.m16n8k16.row.col.f32.bf16.bf16.f32 "
        "{%0,%1,%2,%3}, {%4,%5,%6,%7}, {%8,%9}, {%0,%1,%2,%3};"
        : "+f"(d[0]), "+f"(d[1]), "+f"(d[2]), "+f"(d[3])
        : "r"(a[0]), "r"(a[1]), "r"(a[2]), "r"(a[3]), "r"(b[0]), "r"(b[1]));
}
__device__ __forceinline__ void cp_async16(uint32_t saddr, const void* gptr) {
    asm volatile("cp.async.cg.shared.global [%0], [%1], 16;" :: "r"(saddr), "l"(gptr));
}
__device__ __forceinline__ void cp_async_commit() {
    asm volatile("cp.async.commit_group;" ::: "memory");
}
__device__ __forceinline__ void cp_async_wait0() {
    asm volatile("cp.async.wait_group 0;" ::: "memory");
}

// ---- GEMM2/3 smem layout (R13 proven): A rows 144B, B rows 272B ----
#define LDA_B 144
#define LDB_B 272
#define SM_BIAS 0
#define SM_LNW  512
#define SM_LNB  1024
#define SM_AHI  1536
#define SM_ALO  (SM_AHI + 256*LDA_B)      // 38400
#define SM_BHI  (SM_ALO + 256*LDA_B)      // 75264
#define SM_BLO  (SM_BHI + 128*LDB_B)      // 110080
#define SM_END  (SM_BLO + 128*LDB_B)      // 144896
#define DSMEM_BYTES SM_END

// ---- GEMM1 smem layout: full-K A (272B rows), cp.async'd pre-split ----
#define LDA2 272
#define G1_BIAS 0
#define G1_AHI  512
#define G1_ALO  (G1_AHI + 256*LDA2)       // 70144
#define G1_BHI  (G1_ALO + 256*LDA2)       // 139776
#define G1_BLO  (G1_BHI + 128*LDB_B)      // 174592
#define G1_END  (G1_BLO + 128*LDB_B)      // 209408
#define DSMEM1_BYTES G1_END

// ---------------- CSR build (proven) ----------------

__global__ void k_zero() {
    int i = blockIdx.x * blockDim.x + threadIdx.x;
    if (i <= NND) g_deg[i] = 0;
    if (i < 3) { g_sum[i] = 0.0; g_sumsq[i] = 0.0; }
    // zero the padded tail rows of the pre-split h buffers
    if (i < (NND_PAD - NND) * D) {
        g_hhi[NND * D + i] = __float2bfloat16(0.f);
        g_hlo[NND * D + i] = __float2bfloat16(0.f);
    }
}

__global__ void k_count(const int* __restrict__ ei, int E) {
    int e = blockIdx.x * blockDim.x + threadIdx.x;
    if (e < E) atomicAdd(&g_deg[__ldg(ei + E + e)], 1);
}

__global__ void __launch_bounds__(1024) k_scan1() {
    __shared__ int s[1024];
    int t = threadIdx.x;
    int i = blockIdx.x * 1024 + t;
    int v = (i < NND) ? g_deg[i] : 0;
    s[t] = v;
    __syncthreads();
    #pragma unroll
    for (int o = 1; o < 1024; o <<= 1) {
        int add = (t >= o) ? s[t - o] : 0;
        __syncthreads();
        s[t] += add;
        __syncthreads();
    }
    if (i <= NND) g_off[i] = s[t] - v;
    if (t == 1023) g_blocksum[blockIdx.x] = s[t];
}

__global__ void __launch_bounds__(128) k_scan2() {
    __shared__ int s[128];
    int t = threadIdx.x;
    int v = (t < NBLK) ? g_blocksum[t] : 0;
    s[t] = v;
    __syncthreads();
    #pragma unroll
    for (int o = 1; o < 128; o <<= 1) {
        int add = (t >= o) ? s[t - o] : 0;
        __syncthreads();
        s[t] += add;
        __syncthreads();
    }
    g_blockoff[t] = s[t] - v;
}

__global__ void k_scan3(int E) {
    int i = blockIdx.x * blockDim.x + threadIdx.x;
    if (i < NND) {
        int off = g_off[i] + g_blockoff[i >> 10];
        g_off[i] = off;
        g_cursor[i] = off;
    }
    if (i == 0) g_off[NND] = E;
}

__global__ void k_fill(const int* __restrict__ ei, int E) {
    int e = blockIdx.x * blockDim.x + threadIdx.x;
    if (e >= E) return;
    int dst = __ldg(ei + E + e);
    int src = __ldg(ei + e);
    int pos = atomicAdd(&g_cursor[dst], 1);
    g_srcs[pos] = src;
}

// h[n] = (1+eps)*node[n] + sum node[src]; output pre-split to bf16 hi/lo.
__global__ void __launch_bounds__(256) k_aggr(const float* __restrict__ node,
                                              const float* __restrict__ eps_p) {
    int warp = (blockIdx.x * blockDim.x + threadIdx.x) >> 5;
    int lane = threadIdx.x & 31;
    if (warp >= NND) return;
    int n = warp;
    float s = 1.0f + __ldg(eps_p);
    const float4* nodes = (const float4*)node;
    float4 acc = __ldg(nodes + (long long)n * 32 + lane);
    acc.x *= s; acc.y *= s; acc.z *= s; acc.w *= s;
    int j   = g_off[n];
    int end = g_off[n + 1];
    for (; j + 4 <= end; j += 4) {
        int s0 = __ldg(&g_srcs[j + 0]);
        int s1 = __ldg(&g_srcs[j + 1]);
        int s2 = __ldg(&g_srcs[j + 2]);
        int s3 = __ldg(&g_srcs[j + 3]);
        float4 v0 = __ldg(nodes + (long long)s0 * 32 + lane);
        float4 v1 = __ldg(nodes + (long long)s1 * 32 + lane);
        float4 v2 = __ldg(nodes + (long long)s2 * 32 + lane);
        float4 v3 = __ldg(nodes + (long long)s3 * 32 + lane);
        acc.x += v0.x + v1.x + v2.x + v3.x;
        acc.y += v0.y + v1.y + v2.y + v3.y;
        acc.z += v0.z + v1.z + v2.z + v3.z;
        acc.w += v0.w + v1.w + v2.w + v3.w;
    }
    for (; j < end; ++j) {
        int s0 = __ldg(&g_srcs[j]);
        float4 v0 = __ldg(nodes + (long long)s0 * 32 + lane);
        acc.x += v0.x; acc.y += v0.y; acc.z += v0.z; acc.w += v0.w;
    }
    // split hi/lo (identical math to the old GEMM1 A-phase)
    __nv_bfloat162 h01 = __float22bfloat162_rn(make_float2(acc.x, acc.y));
    __nv_bfloat162 h23 = __float22bfloat162_rn(make_float2(acc.z, acc.w));
    float2 f01 = __bfloat1622float2(h01);
    float2 f23 = __bfloat1622float2(h23);
    __nv_bfloat162 l01 = __float22bfloat162_rn(make_float2(acc.x - f01.x, acc.y - f01.y));
    __nv_bfloat162 l23 = __float22bfloat162_rn(make_float2(acc.z - f23.x, acc.w - f23.y));
    long long o = (long long)n * D + lane * 4;
    *(uint2*)(g_hhi + o) = make_uint2(*(uint32_t*)&h01, *(uint32_t*)&h23);
    *(uint2*)(g_hlo + o) = make_uint2(*(uint32_t*)&l01, *(uint32_t*)&l23);
}

// ---------------- Weight prep: fp32 -> bf16 hi/lo, [k][n] ----------------

__global__ void k_prepw(const float* __restrict__ W,
                        __nv_bfloat16* __restrict__ hi, __nv_bfloat16* __restrict__ lo) {
    int idx = blockIdx.x * blockDim.x + threadIdx.x;
    if (idx >= 16384) return;
    float w = __ldg(W + idx);
    __nv_bfloat16 h = __float2bfloat16_rn(w);
    float l = w - __bfloat162float(h);
    hi[idx] = h;
    lo[idx] = __float2bfloat16_rn(l);
}

// ---------------- GEMM1: persistent, pre-split A via cp.async ----------------
// Y = h @ W1 + b1; h already bf16 hi/lo in g_hhi/g_hlo. Per tile: one cp.async
// burst (full-K A), one sync, 8 k-steps of MMA, epilogue with LN sums (idx 0).
__global__ void __launch_bounds__(512)
k_gemm1(const __nv_bfloat16* __restrict__ whi, const __nv_bfloat16* __restrict__ wlo,
        const float* __restrict__ bias, float* __restrict__ Y, int M)
{
    extern __shared__ char sm[];
    const uint32_t sb = smem_u32(sm);
    const int t    = threadIdx.x;
    const int wid  = t >> 5;
    const int lane = t & 31;
    const int wm   = wid & 3;        // 64-row band
    const int wn   = wid >> 2;       // 32-col band

    // B (full K, hi+lo) once per CTA.
    #pragma unroll
    for (int it = 0; it < 4; ++it) {
        int idx  = t + it * 512;
        int kr   = idx >> 4;
        int ncol = (idx & 15) * 8;
        uint32_t soff = kr * LDB_B + ncol * 2;
        long long goff = (long long)kr * 128 + ncol;
        cp_async16(sb + G1_BHI + soff, whi + goff);
        cp_async16(sb + G1_BLO + soff, wlo + goff);
    }
    cp_async_commit();

    float* s_bias = (float*)(sm + G1_BIAS);
    if (t < 128) s_bias[t] = bias[t];
    cp_async_wait0();
    __syncthreads();

    for (int tile = blockIdx.x; tile < NTILES; tile += gridDim.x) {
        const int row0 = tile * 256;

        __syncthreads();   // previous tile's MMA done before overwriting A smem
        // Full-K A tile, pre-split, pure cp.async: 256 rows x 16 16B-units x2.
        #pragma unroll
        for (int it = 0; it < 8; ++it) {
            int idx = t + it * 512;          // 0..4095
            int r   = idx >> 4;              // 0..255
            int u   = idx & 15;              // 16B unit within row
            uint32_t soff = r * LDA2 + u * 16;
            long long goff = (long long)(row0 + r) * D + u * 8;
            cp_async16(sb + G1_AHI + soff, g_hhi + goff);
            cp_async16(sb + G1_ALO + soff, g_hlo + goff);
        }
        cp_async_commit();
        cp_async_wait0();
        __syncthreads();

        float acc[4][4][4];
        #pragma unroll
        for (int i = 0; i < 4; ++i)
            #pragma unroll
            for (int j = 0; j < 4; ++j)
                #pragma unroll
                for (int q = 0; q < 4; ++q) acc[i][j][q] = 0.f;

        // 8 k16 steps over full K.
        #pragma unroll
        for (int ks = 0; ks < 8; ++ks) {
            int kk = ks * 16;
            uint32_t Bh[2][4], Bl[2][4];
            {
                int g  = lane >> 3;
                int l8 = lane & 7;
                int brow = kk + (g & 1) * 8 + l8;
                #pragma unroll
                for (int p = 0; p < 2; ++p) {
                    int bcol = 32 * wn + p * 16 + (g >> 1) * 8;
                    uint32_t bo = sb + G1_BHI + brow * LDB_B + bcol * 2;
                    ldsm_x4_t(Bh[p], bo);
                    ldsm_x4_t(Bl[p], bo + (G1_BLO - G1_BHI));
                }
            }
            #pragma unroll
            for (int mt = 0; mt < 4; ++mt) {
                uint32_t Ah[4], Al[4];
                int arow = 64 * wm + 16 * mt + (lane & 15);
                int acol = kk + 8 * (lane >> 4);
                uint32_t ao = sb + G1_AHI + arow * LDA2 + acol * 2;
                ldsm_x4(Ah, ao);
                ldsm_x4(Al, ao + (G1_ALO - G1_AHI));
                #pragma unroll
                for (int p = 0; p < 2; ++p) {
                    mma_bf16(acc[mt][2*p],   Ah, Bh[p]);
                    mma_bf16(acc[mt][2*p+1], Ah, Bh[p] + 2);
                    mma_bf16(acc[mt][2*p],   Ah, Bl[p]);
                    mma_bf16(acc[mt][2*p+1], Ah, Bl[p] + 2);
                    mma_bf16(acc[mt][2*p],   Al, Bh[p]);
                    mma_bf16(acc[mt][2*p+1], Al, Bh[p] + 2);
                }
            }
        }

        // Epilogue: bias, store, LN sums (idx 0).
        float lsum = 0.f, lsq = 0.f;
        #pragma unroll
        for (int mt = 0; mt < 4; ++mt) {
            #pragma unroll
            for (int nt = 0; nt < 4; ++nt) {
                int r = row0 + 64 * wm + 16 * mt + (lane >> 2);
                int c = 32 * wn + 8 * nt + 2 * (lane & 3);
                float b0 = s_bias[c], b1 = s_bias[c + 1];
                if (r < M) {
                    float2 v = make_float2(acc[mt][nt][0] + b0, acc[mt][nt][1] + b1);
                    lsum += v.x + v.y;
                    lsq  += v.x * v.x + v.y * v.y;
                    *(float2*)(Y + (long long)r * D + c) = v;
                }
                if (r + 8 < M) {
                    float2 v = make_float2(acc[mt][nt][2] + b0, acc[mt][nt][3] + b1);
                    lsum += v.x + v.y;
                    lsq  += v.x * v.x + v.y * v.y;
                    *(float2*)(Y + (long long)(r + 8) * D + c) = v;
                }
            }
        }
        #pragma unroll
        for (int o = 16; o > 0; o >>= 1) {
            lsum += __shfl_down_sync(0xffffffffu, lsum, o);
            lsq  += __shfl_down_sync(0xffffffffu, lsq, o);
        }
        if (lane == 0) {
            atomicAdd(&g_sum[0],   (double)lsum);
            atomicAdd(&g_sumsq[0], (double)lsq);
        }
    }
}

// ---------------- GEMM2/3: persistent warp-MMA bf16x3 (R13 proven) ----------------
__global__ void __launch_bounds__(512)
k_gemm_mma(const float* __restrict__ A,
           const __nv_bfloat16* __restrict__ whi, const __nv_bfloat16* __restrict__ wlo,
           const float* __restrict__ bias,
           const float* __restrict__ lnw, const float* __restrict__ lnb,
           int sidx_in, int sidx_out,
           float* __restrict__ Y, int M)
{
    extern __shared__ char sm[];
    const uint32_t sb = smem_u32(sm);
    const int t    = threadIdx.x;
    const int wid  = t >> 5;
    const int lane = t & 31;
    const int wm   = wid & 3;
    const int wn   = wid >> 2;

    #pragma unroll
    for (int it = 0; it < 4; ++it) {
        int idx  = t + it * 512;
        int kr   = idx >> 4;
        int ncol = (idx & 15) * 8;
        uint32_t soff = kr * LDB_B + ncol * 2;
        long long goff = (long long)kr * 128 + ncol;
        cp_async16(sb + SM_BHI + soff, whi + goff);
        cp_async16(sb + SM_BLO + soff, wlo + goff);
    }
    cp_async_commit();

    float* s_bias = (float*)(sm + SM_BIAS);
    float* s_lnw  = (float*)(sm + SM_LNW);
    float* s_lnb  = (float*)(sm + SM_LNB);
    if (t < 128) {
        s_bias[t] = bias[t];
        s_lnw[t] = lnw[t];
        s_lnb[t] = lnb[t];
    }
    float mu, inv;
    {
        double m = g_sum[sidx_in] * (1.0 / (double)NELEM);
        double v = g_sumsq[sidx_in] * (1.0 / (double)NELEM) - m * m;
        if (v < 0.0) v = 0.0;
        mu  = (float)m;
        inv = 1.0f / (sqrtf((float)v) + 1e-5f);
    }
    cp_async_wait0();
    __syncthreads();

    for (int tile = blockIdx.x; tile < NTILES; tile += gridDim.x) {
        const int row0 = tile * 256;

        float acc[4][4][4];
        #pragma unroll
        for (int i = 0; i < 4; ++i)
            #pragma unroll
            for (int j = 0; j < 4; ++j)
                #pragma unroll
                for (int q = 0; q < 4; ++q) acc[i][j][q] = 0.f;

        #pragma unroll
        for (int kc = 0; kc < 2; ++kc) {
            __syncthreads();

            #pragma unroll
            for (int it = 0; it < 8; ++it) {
                int idx = t + it * 512;
                int r   = idx >> 4;
                int kl  = (idx & 15) * 4;
                int grow = row0 + r;
                float4 v = make_float4(0.f, 0.f, 0.f, 0.f);
                if (grow < M) v = __ldg((const float4*)(A + (long long)grow * D + kc * 64 + kl));
                int k0 = kc * 64 + kl;
                v.x = fmaxf((v.x - mu) * inv * s_lnw[k0+0] + s_lnb[k0+0], 0.f);
                v.y = fmaxf((v.y - mu) * inv * s_lnw[k0+1] + s_lnb[k0+1], 0.f);
                v.z = fmaxf((v.z - mu) * inv * s_lnw[k0+2] + s_lnb[k0+2], 0.f);
                v.w = fmaxf((v.w - mu) * inv * s_lnw[k0+3] + s_lnb[k0+3], 0.f);
                __nv_bfloat162 h01 = __float22bfloat162_rn(make_float2(v.x, v.y));
                __nv_bfloat162 h23 = __float22bfloat162_rn(make_float2(v.z, v.w));
                float2 hf01 = __bfloat1622float2(h01);
                float2 hf23 = __bfloat1622float2(h23);
                __nv_bfloat162 l01 = __float22bfloat162_rn(make_float2(v.x - hf01.x, v.y - hf01.y));
                __nv_bfloat162 l23 = __float22bfloat162_rn(make_float2(v.z - hf23.x, v.w - hf23.y));
                uint32_t off = r * LDA_B + kl * 2;
                *(uint2*)(sm + SM_AHI + off) = make_uint2(*(uint32_t*)&h01, *(uint32_t*)&h23);
                *(uint2*)(sm + SM_ALO + off) = make_uint2(*(uint32_t*)&l01, *(uint32_t*)&l23);
            }
            __syncthreads();

            #pragma unroll
            for (int ks = 0; ks < 4; ++ks) {
                int kk = ks * 16;
                uint32_t Bh[2][4], Bl[2][4];
                {
                    int g  = lane >> 3;
                    int l8 = lane & 7;
                    int brow = kc * 64 + kk + (g & 1) * 8 + l8;
                    #pragma unroll
                    for (int p = 0; p < 2; ++p) {
                        int bcol = 32 * wn + p * 16 + (g >> 1) * 8;
                        uint32_t bo = sb + SM_BHI + brow * LDB_B + bcol * 2;
                        ldsm_x4_t(Bh[p], bo);
                        ldsm_x4_t(Bl[p], bo + (SM_BLO - SM_BHI));
                    }
                }
                #pragma unroll
                for (int mt = 0; mt < 4; ++mt) {
                    uint32_t Ah[4], Al[4];
                    int arow = 64 * wm + 16 * mt + (lane & 15);
                    int acol = kk + 8 * (lane >> 4);
                    uint32_t ao = sb + SM_AHI + arow * LDA_B + acol * 2;
                    ldsm_x4(Ah, ao);
                    ldsm_x4(Al, ao + (SM_ALO - SM_AHI));
                    #pragma unroll
                    for (int p = 0; p < 2; ++p) {
                        mma_bf16(acc[mt][2*p],   Ah, Bh[p]);
                        mma_bf16(acc[mt][2*p+1], Ah, Bh[p] + 2);
                        mma_bf16(acc[mt][2*p],   Ah, Bl[p]);
                        mma_bf16(acc[mt][2*p+1], Ah, Bl[p] + 2);
                        mma_bf16(acc[mt][2*p],   Al, Bh[p]);
                        mma_bf16(acc[mt][2*p+1], Al, Bh[p] + 2);
                    }
                }
            }
        }

        float lsum = 0.f, lsq = 0.f;
        #pragma unroll
        for (int mt = 0; mt < 4; ++mt) {
            #pragma unroll
            for (int nt = 0; nt < 4; ++nt) {
                int r = row0 + 64 * wm + 16 * mt + (lane >> 2);
                int c = 32 * wn + 8 * nt + 2 * (lane & 3);
                float b0 = s_bias[c], b1 = s_bias[c + 1];
                if (r < M) {
                    float2 v = make_float2(acc[mt][nt][0] + b0, acc[mt][nt][1] + b1);
                    lsum += v.x + v.y;
                    lsq  += v.x * v.x + v.y * v.y;
                    *(float2*)(Y + (long long)r * D + c) = v;
                }
                if (r + 8 < M) {
                    float2 v = make_float2(acc[mt][nt][2] + b0, acc[mt][nt][3] + b1);
                    lsum += v.x + v.y;
                    lsq  += v.x * v.x + v.y * v.y;
                    *(float2*)(Y + (long long)(r + 8) * D + c) = v;
                }
            }
        }
        #pragma unroll
        for (int o = 16; o > 0; o >>= 1) {
            lsum += __shfl_down_sync(0xffffffffu, lsum, o);
            lsq  += __shfl_down_sync(0xffffffffu, lsq, o);
        }
        if (lane == 0) {
            atomicAdd(&g_sum[sidx_out],   (double)lsum);
            atomicAdd(&g_sumsq[sidx_out], (double)lsq);
        }
    }
}

// out = relu(graph_layernorm(Y)), sums at index 2.
__global__ void k_apply_out(const float* __restrict__ Y, const float* __restrict__ w,
                            const float* __restrict__ b, float* __restrict__ out) {
    long long i = blockIdx.x * (long long)blockDim.x + threadIdx.x;
    if (i >= NELEM/4) return;
    double m = g_sum[2] * (1.0 / (double)NELEM);
    double v = g_sumsq[2] * (1.0 / (double)NELEM) - m * m;
    if (v < 0.0) v = 0.0;
    float mu  = (float)m;
    float inv = 1.0f / (sqrtf((float)v) + 1e-5f);
    int k = ((int)i * 4) & 127;
    float4 val = __ldg((const float4*)Y + i);
    float4 o;
    o.x = fmaxf((val.x - mu) * inv * __ldg(w + k + 0) + __ldg(b + k + 0), 0.f);
    o.y = fmaxf((val.y - mu) * inv * __ldg(w + k + 1) + __ldg(b + k + 1), 0.f);
    o.z = fmaxf((val.z - mu) * inv * __ldg(w + k + 2) + __ldg(b + k + 2), 0.f);
    o.w = fmaxf((val.w - mu) * inv * __ldg(w + k + 3) + __ldg(b + k + 3), 0.f);
    ((float4*)out)[i] = o;
}

extern "C" void kernel_launch(void* const* d_in, const int* in_sizes, int n_in,
                              void* d_out, int out_size) {
    const float* node = (const float*)d_in[0];
    const int*   ei   = (const int*)d_in[1];
    const float* eps  = (const float*)d_in[4];
    const float* W1   = (const float*)d_in[5];
    const float* b1   = (const float*)d_in[6];
    const float* ln1w = (const float*)d_in[7];
    const float* ln1b = (const float*)d_in[8];
    const float* W2   = (const float*)d_in[9];
    const float* b2   = (const float*)d_in[10];
    const float* ln2w = (const float*)d_in[11];
    const float* ln2b = (const float*)d_in[12];
    const float* W3   = (const float*)d_in[13];
    const float* b3   = (const float*)d_in[14];
    const float* lnow = (const float*)d_in[15];
    const float* lnob = (const float*)d_in[16];

    int E = in_sizes[1] / 2;

    void *p0, *p1, *pw;
    cudaGetSymbolAddress(&p0, g_buf0);
    cudaGetSymbolAddress(&p1, g_buf1);
    cudaGetSymbolAddress(&pw, g_wimg);
    float* buf0 = (float*)p0;
    float* buf1 = (float*)p1;
    __nv_bfloat16* wimg = (__nv_bfloat16*)pw;   // [3][2][16384]

    cudaFuncSetAttribute(k_gemm1,   cudaFuncAttributeMaxDynamicSharedMemorySize, DSMEM1_BYTES);
    cudaFuncSetAttribute(k_gemm_mma, cudaFuncAttributeMaxDynamicSharedMemorySize, DSMEM_BYTES);

    // Weight prep
    k_prepw<<<64, 256>>>(W1, wimg + 0*32768, wimg + 0*32768 + 16384);
    k_prepw<<<64, 256>>>(W2, wimg + 1*32768, wimg + 1*32768 + 16384);
    k_prepw<<<64, 256>>>(W3, wimg + 2*32768, wimg + 2*32768 + 16384);

    // CSR build
    k_zero<<<(NND + 1024) / 1024, 1024>>>();
    k_count<<<(E + 255) / 256, 256>>>(ei, E);
    k_scan1<<<NBLK, 1024>>>();
    k_scan2<<<1, 128>>>();
    k_scan3<<<(NND + 255) / 256, 256>>>(E);
    k_fill<<<(E + 255) / 256, 256>>>(ei, E);

    // Aggregation: h = (1+eps)*node + gather-sum, pre-split to bf16 hi/lo.
    k_aggr<<<(NND * 32 + 255) / 256, 256>>>(node, eps);

    // GEMM layers (persistent)
    k_gemm1<<<GEMM_GRID, 512, DSMEM1_BYTES>>>(wimg + 0*32768, wimg + 0*32768 + 16384,
                                              b1, buf1, NND);
    k_gemm_mma<<<GEMM_GRID, 512, DSMEM_BYTES>>>(buf1, wimg + 1*32768, wimg + 1*32768 + 16384,
                                                b2, ln1w, ln1b, 0, 1, buf0, NND);
    k_gemm_mma<<<GEMM_GRID, 512, DSMEM_BYTES>>>(buf0, wimg + 2*32768, wimg + 2*32768 + 16384,
                                                b3, ln2w, ln2b, 1, 2, buf1, NND);

    int nb_elem = (NELEM/4 + 255) / 256;
    k_apply_out<<<nb_elem, 256>>>(buf1, lnow, lnob, (float*)d_out);
}

// round 17
// speedup vs baseline: 1.0071x; 1.0071x over previous
#include <cuda_runtime.h>
#include <cuda_bf16.h>
#include <math.h>
#include <stdint.h>

#define NND 100000
#define D 128
#define NELEM (NND*D)
#define EMAX 2000000
#define NBLK 98           // ceil(100000/1024)
#define NTILES 391        // ceil(100000/256)
#define NND_PAD (NTILES*256)   // 100096
#define GEMM_GRID 148

// Scratch (allocation-free)
__device__ float  g_buf0[NELEM];
__device__ float  g_buf1[NELEM];
__device__ double g_sum[3];
__device__ double g_sumsq[3];
__device__ int    g_deg[NND + 1];
__device__ int    g_off[NND + 1];
__device__ int    g_cursor[NND];
__device__ int    g_srcs[EMAX];
__device__ int    g_blocksum[128];
__device__ int    g_blockoff[128];
// h = GIN-aggregated features, pre-split to bf16 hi/lo (padded to tile grid).
__device__ __nv_bfloat16 g_hhi[NND_PAD * D];
__device__ __nv_bfloat16 g_hlo[NND_PAD * D];
// bf16 hi/lo images of the three weight matrices, [k][n] row-major.
__device__ __nv_bfloat16 g_wimg[3][2][16384];

__device__ __forceinline__ uint32_t smem_u32(const void* p) {
    uint32_t a;
    asm("{ .reg .u64 t; cvta.to.shared.u64 t, %1; cvt.u32.u64 %0, t; }" : "=r"(a) : "l"(p));
    return a;
}

__device__ __forceinline__ void ldsm_x4(uint32_t* r, uint32_t addr) {
    asm volatile("ldmatrix.sync.aligned.m8n8.x4.shared.b16 {%0,%1,%2,%3}, [%4];"
                 : "=r"(r[0]), "=r"(r[1]), "=r"(r[2]), "=r"(r[3]) : "r"(addr));
}
__device__ __forceinline__ void ldsm_x4_t(uint32_t* r, uint32_t addr) {
    asm volatile("ldmatrix.sync.aligned.m8n8.x4.trans.shared.b16 {%0,%1,%2,%3}, [%4];"
                 : "=r"(r[0]), "=r"(r[1]), "=r"(r[2]), "=r"(r[3]) : "r"(addr));
}
__device__ __forceinline__ void mma_bf16(float* d, const uint32_t* a, const uint32_t* b) {
    asm volatile(
        "mma.sync.aligned.m16n8k16.row.col.f32.bf16.bf16.f32 "
        "{%0,%1,%2,%3}, {%4,%5,%6,%7}, {%8,%9}, {%0,%1,%2,%3};"
        : "+f"(d[0]), "+f"(d[1]), "+f"(d[2]), "+f"(d[3])
        : "r"(a[0]), "r"(a[1]), "r"(a[2]), "r"(a[3]), "r"(b[0]), "r"(b[1]));
}
__device__ __forceinline__ void cp_async16(uint32_t saddr, const void* gptr) {
    asm volatile("cp.async.cg.shared.global [%0], [%1], 16;" :: "r"(saddr), "l"(gptr));
}
__device__ __forceinline__ void cp_async_commit() {
    asm volatile("cp.async.commit_group;" ::: "memory");
}
__device__ __forceinline__ void cp_async_wait0() {
    asm volatile("cp.async.wait_group 0;" ::: "memory");
}

// ---- GEMM2/3 smem layout (R13 proven): A rows 144B, B rows 272B ----
#define LDA_B 144
#define LDB_B 272
#define SM_BIAS 0
#define SM_LNW  512
#define SM_LNB  1024
#define SM_AHI  1536
#define SM_ALO  (SM_AHI + 256*LDA_B)      // 38400
#define SM_BHI  (SM_ALO + 256*LDA_B)      // 75264
#define SM_BLO  (SM_BHI + 128*LDB_B)      // 110080
#define SM_END  (SM_BLO + 128*LDB_B)      // 144896
#define DSMEM_BYTES SM_END

// ---- GEMM1 smem layout: full-K A (272B rows), cp.async'd pre-split ----
#define LDA2 272
#define G1_BIAS 0
#define G1_AHI  512
#define G1_ALO  (G1_AHI + 256*LDA2)       // 70144
#define G1_BHI  (G1_ALO + 256*LDA2)       // 139776
#define G1_BLO  (G1_BHI + 128*LDB_B)      // 174592
#define G1_END  (G1_BLO + 128*LDB_B)      // 209408
#define DSMEM1_BYTES G1_END

// ---------------- CSR build (proven) ----------------

__global__ void k_zero() {
    int i = blockIdx.x * blockDim.x + threadIdx.x;
    if (i <= NND) g_deg[i] = 0;
    if (i < 3) { g_sum[i] = 0.0; g_sumsq[i] = 0.0; }
    // zero the padded tail rows of the pre-split h buffers
    if (i < (NND_PAD - NND) * D) {
        g_hhi[NND * D + i] = __float2bfloat16(0.f);
        g_hlo[NND * D + i] = __float2bfloat16(0.f);
    }
}

__global__ void k_count(const int* __restrict__ ei, int E) {
    int e = blockIdx.x * blockDim.x + threadIdx.x;
    if (e < E) atomicAdd(&g_deg[__ldg(ei + E + e)], 1);
}

__global__ void __launch_bounds__(1024) k_scan1() {
    __shared__ int s[1024];
    int t = threadIdx.x;
    int i = blockIdx.x * 1024 + t;
    int v = (i < NND) ? g_deg[i] : 0;
    s[t] = v;
    __syncthreads();
    #pragma unroll
    for (int o = 1; o < 1024; o <<= 1) {
        int add = (t >= o) ? s[t - o] : 0;
        __syncthreads();
        s[t] += add;
        __syncthreads();
    }
    if (i <= NND) g_off[i] = s[t] - v;
    if (t == 1023) g_blocksum[blockIdx.x] = s[t];
}

__global__ void __launch_bounds__(128) k_scan2() {
    __shared__ int s[128];
    int t = threadIdx.x;
    int v = (t < NBLK) ? g_blocksum[t] : 0;
    s[t] = v;
    __syncthreads();
    #pragma unroll
    for (int o = 1; o < 128; o <<= 1) {
        int add = (t >= o) ? s[t - o] : 0;
        __syncthreads();
        s[t] += add;
        __syncthreads();
    }
    g_blockoff[t] = s[t] - v;
}

__global__ void k_scan3(int E) {
    int i = blockIdx.x * blockDim.x + threadIdx.x;
    if (i < NND) {
        int off = g_off[i] + g_blockoff[i >> 10];
        g_off[i] = off;
        g_cursor[i] = off;
    }
    if (i == 0) g_off[NND] = E;
}

__global__ void k_fill(const int* __restrict__ ei, int E) {
    int e = blockIdx.x * blockDim.x + threadIdx.x;
    if (e >= E) return;
    int dst = __ldg(ei + E + e);
    int src = __ldg(ei + e);
    int pos = atomicAdd(&g_cursor[dst], 1);
    g_srcs[pos] = src;
}

// h[n] = (1+eps)*node[n] + sum node[src]; output pre-split to bf16 hi/lo.
__global__ void __launch_bounds__(256) k_aggr(const float* __restrict__ node,
                                              const float* __restrict__ eps_p) {
    int warp = (blockIdx.x * blockDim.x + threadIdx.x) >> 5;
    int lane = threadIdx.x & 31;
    if (warp >= NND) return;
    int n = warp;
    float s = 1.0f + __ldg(eps_p);
    const float4* nodes = (const float4*)node;
    float4 acc = __ldg(nodes + (long long)n * 32 + lane);
    acc.x *= s; acc.y *= s; acc.z *= s; acc.w *= s;
    int j   = g_off[n];
    int end = g_off[n + 1];
    for (; j + 4 <= end; j += 4) {
        int s0 = __ldg(&g_srcs[j + 0]);
        int s1 = __ldg(&g_srcs[j + 1]);
        int s2 = __ldg(&g_srcs[j + 2]);
        int s3 = __ldg(&g_srcs[j + 3]);
        float4 v0 = __ldg(nodes + (long long)s0 * 32 + lane);
        float4 v1 = __ldg(nodes + (long long)s1 * 32 + lane);
        float4 v2 = __ldg(nodes + (long long)s2 * 32 + lane);
        float4 v3 = __ldg(nodes + (long long)s3 * 32 + lane);
        acc.x += v0.x + v1.x + v2.x + v3.x;
        acc.y += v0.y + v1.y + v2.y + v3.y;
        acc.z += v0.z + v1.z + v2.z + v3.z;
        acc.w += v0.w + v1.w + v2.w + v3.w;
    }
    for (; j < end; ++j) {
        int s0 = __ldg(&g_srcs[j]);
        float4 v0 = __ldg(nodes + (long long)s0 * 32 + lane);
        acc.x += v0.x; acc.y += v0.y; acc.z += v0.z; acc.w += v0.w;
    }
    // split hi/lo (identical math to the old GEMM1 A-phase)
    __nv_bfloat162 h01 = __float22bfloat162_rn(make_float2(acc.x, acc.y));
    __nv_bfloat162 h23 = __float22bfloat162_rn(make_float2(acc.z, acc.w));
    float2 f01 = __bfloat1622float2(h01);
    float2 f23 = __bfloat1622float2(h23);
    __nv_bfloat162 l01 = __float22bfloat162_rn(make_float2(acc.x - f01.x, acc.y - f01.y));
    __nv_bfloat162 l23 = __float22bfloat162_rn(make_float2(acc.z - f23.x, acc.w - f23.y));
    long long o = (long long)n * D + lane * 4;
    *(uint2*)(g_hhi + o) = make_uint2(*(uint32_t*)&h01, *(uint32_t*)&h23);
    *(uint2*)(g_hlo + o) = make_uint2(*(uint32_t*)&l01, *(uint32_t*)&l23);
}

// ---------------- Weight prep: fp32 -> bf16 hi/lo, [k][n] ----------------

__global__ void k_prepw(const float* __restrict__ W,
                        __nv_bfloat16* __restrict__ hi, __nv_bfloat16* __restrict__ lo) {
    int idx = blockIdx.x * blockDim.x + threadIdx.x;
    if (idx >= 16384) return;
    float w = __ldg(W + idx);
    __nv_bfloat16 h = __float2bfloat16_rn(w);
    float l = w - __bfloat162float(h);
    hi[idx] = h;
    lo[idx] = __float2bfloat16_rn(l);
}

// ---------------- GEMM1: persistent, pre-split A via cp.async ----------------
// Y = h @ W1 + b1; h already bf16 hi/lo in g_hhi/g_hlo. Per tile: one cp.async
// burst (full-K A), one sync, 8 k-steps of MMA, epilogue with LN sums (idx 0).
__global__ void __launch_bounds__(512)
k_gemm1(const __nv_bfloat16* __restrict__ whi, const __nv_bfloat16* __restrict__ wlo,
        const float* __restrict__ bias, float* __restrict__ Y, int M)
{
    extern __shared__ char sm[];
    const uint32_t sb = smem_u32(sm);
    const int t    = threadIdx.x;
    const int wid  = t >> 5;
    const int lane = t & 31;
    const int wm   = wid & 3;        // 64-row band
    const int wn   = wid >> 2;       // 32-col band

    // B (full K, hi+lo) once per CTA.
    #pragma unroll
    for (int it = 0; it < 4; ++it) {
        int idx  = t + it * 512;
        int kr   = idx >> 4;
        int ncol = (idx & 15) * 8;
        uint32_t soff = kr * LDB_B + ncol * 2;
        long long goff = (long long)kr * 128 + ncol;
        cp_async16(sb + G1_BHI + soff, whi + goff);
        cp_async16(sb + G1_BLO + soff, wlo + goff);
    }
    cp_async_commit();

    float* s_bias = (float*)(sm + G1_BIAS);
    if (t < 128) s_bias[t] = bias[t];
    cp_async_wait0();
    __syncthreads();

    for (int tile = blockIdx.x; tile < NTILES; tile += gridDim.x) {
        const int row0 = tile * 256;

        __syncthreads();   // previous tile's MMA done before overwriting A smem
        // Full-K A tile, pre-split, pure cp.async: 256 rows x 16 16B-units x2.
        #pragma unroll
        for (int it = 0; it < 8; ++it) {
            int idx = t + it * 512;          // 0..4095
            int r   = idx >> 4;              // 0..255
            int u   = idx & 15;              // 16B unit within row
            uint32_t soff = r * LDA2 + u * 16;
            long long goff = (long long)(row0 + r) * D + u * 8;
            cp_async16(sb + G1_AHI + soff, g_hhi + goff);
            cp_async16(sb + G1_ALO + soff, g_hlo + goff);
        }
        cp_async_commit();
        cp_async_wait0();
        __syncthreads();

        float acc[4][4][4];
        #pragma unroll
        for (int i = 0; i < 4; ++i)
            #pragma unroll
            for (int j = 0; j < 4; ++j)
                #pragma unroll
                for (int q = 0; q < 4; ++q) acc[i][j][q] = 0.f;

        // 8 k16 steps over full K.
        #pragma unroll
        for (int ks = 0; ks < 8; ++ks) {
            int kk = ks * 16;
            uint32_t Bh[2][4], Bl[2][4];
            {
                int g  = lane >> 3;
                int l8 = lane & 7;
                int brow = kk + (g & 1) * 8 + l8;
                #pragma unroll
                for (int p = 0; p < 2; ++p) {
                    int bcol = 32 * wn + p * 16 + (g >> 1) * 8;
                    uint32_t bo = sb + G1_BHI + brow * LDB_B + bcol * 2;
                    ldsm_x4_t(Bh[p], bo);
                    ldsm_x4_t(Bl[p], bo + (G1_BLO - G1_BHI));
                }
            }
            #pragma unroll
            for (int mt = 0; mt < 4; ++mt) {
                uint32_t Ah[4], Al[4];
                int arow = 64 * wm + 16 * mt + (lane & 15);
                int acol = kk + 8 * (lane >> 4);
                uint32_t ao = sb + G1_AHI + arow * LDA2 + acol * 2;
                ldsm_x4(Ah, ao);
                ldsm_x4(Al, ao + (G1_ALO - G1_AHI));
                #pragma unroll
                for (int p = 0; p < 2; ++p) {
                    mma_bf16(acc[mt][2*p],   Ah, Bh[p]);
                    mma_bf16(acc[mt][2*p+1], Ah, Bh[p] + 2);
                    mma_bf16(acc[mt][2*p],   Ah, Bl[p]);
                    mma_bf16(acc[mt][2*p+1], Ah, Bl[p] + 2);
                    mma_bf16(acc[mt][2*p],   Al, Bh[p]);
                    mma_bf16(acc[mt][2*p+1], Al, Bh[p] + 2);
                }
            }
        }

        // Epilogue: bias, store, LN sums (idx 0).
        float lsum = 0.f, lsq = 0.f;
        #pragma unroll
        for (int mt = 0; mt < 4; ++mt) {
            #pragma unroll
            for (int nt = 0; nt < 4; ++nt) {
                int r = row0 + 64 * wm + 16 * mt + (lane >> 2);
                int c = 32 * wn + 8 * nt + 2 * (lane & 3);
                float b0 = s_bias[c], b1 = s_bias[c + 1];
                if (r < M) {
                    float2 v = make_float2(acc[mt][nt][0] + b0, acc[mt][nt][1] + b1);
                    lsum += v.x + v.y;
                    lsq  += v.x * v.x + v.y * v.y;
                    *(float2*)(Y + (long long)r * D + c) = v;
                }
                if (r + 8 < M) {
                    float2 v = make_float2(acc[mt][nt][2] + b0, acc[mt][nt][3] + b1);
                    lsum += v.x + v.y;
                    lsq  += v.x * v.x + v.y * v.y;
                    *(float2*)(Y + (long long)(r + 8) * D + c) = v;
                }
            }
        }
        #pragma unroll
        for (int o = 16; o > 0; o >>= 1) {
            lsum += __shfl_down_sync(0xffffffffu, lsum, o);
            lsq  += __shfl_down_sync(0xffffffffu, lsq, o);
        }
        if (lane == 0) {
            atomicAdd(&g_sum[0],   (double)lsum);
            atomicAdd(&g_sumsq[0], (double)lsq);
        }
    }
}

// ---------------- GEMM2/3: persistent warp-MMA bf16x3 (R13 proven) ----------------
__global__ void __launch_bounds__(512)
k_gemm_mma(const float* __restrict__ A,
           const __nv_bfloat16* __restrict__ whi, const __nv_bfloat16* __restrict__ wlo,
           const float* __restrict__ bias,
           const float* __restrict__ lnw, const float* __restrict__ lnb,
           int sidx_in, int sidx_out,
           float* __restrict__ Y, int M)
{
    extern __shared__ char sm[];
    const uint32_t sb = smem_u32(sm);
    const int t    = threadIdx.x;
    const int wid  = t >> 5;
    const int lane = t & 31;
    const int wm   = wid & 3;
    const int wn   = wid >> 2;

    #pragma unroll
    for (int it = 0; it < 4; ++it) {
        int idx  = t + it * 512;
        int kr   = idx >> 4;
        int ncol = (idx & 15) * 8;
        uint32_t soff = kr * LDB_B + ncol * 2;
        long long goff = (long long)kr * 128 + ncol;
        cp_async16(sb + SM_BHI + soff, whi + goff);
        cp_async16(sb + SM_BLO + soff, wlo + goff);
    }
    cp_async_commit();

    float* s_bias = (float*)(sm + SM_BIAS);
    float* s_lnw  = (float*)(sm + SM_LNW);
    float* s_lnb  = (float*)(sm + SM_LNB);
    if (t < 128) {
        s_bias[t] = bias[t];
        s_lnw[t] = lnw[t];
        s_lnb[t] = lnb[t];
    }
    float mu, inv;
    {
        double m = g_sum[sidx_in] * (1.0 / (double)NELEM);
        double v = g_sumsq[sidx_in] * (1.0 / (double)NELEM) - m * m;
        if (v < 0.0) v = 0.0;
        mu  = (float)m;
        inv = 1.0f / (sqrtf((float)v) + 1e-5f);
    }
    cp_async_wait0();
    __syncthreads();

    for (int tile = blockIdx.x; tile < NTILES; tile += gridDim.x) {
        const int row0 = tile * 256;

        float acc[4][4][4];
        #pragma unroll
        for (int i = 0; i < 4; ++i)
            #pragma unroll
            for (int j = 0; j < 4; ++j)
                #pragma unroll
                for (int q = 0; q < 4; ++q) acc[i][j][q] = 0.f;

        #pragma unroll
        for (int kc = 0; kc < 2; ++kc) {
            __syncthreads();

            #pragma unroll
            for (int it = 0; it < 8; ++it) {
                int idx = t + it * 512;
                int r   = idx >> 4;
                int kl  = (idx & 15) * 4;
                int grow = row0 + r;
                float4 v = make_float4(0.f, 0.f, 0.f, 0.f);
                if (grow < M) v = __ldg((const float4*)(A + (long long)grow * D + kc * 64 + kl));
                int k0 = kc * 64 + kl;
                v.x = fmaxf((v.x - mu) * inv * s_lnw[k0+0] + s_lnb[k0+0], 0.f);
                v.y = fmaxf((v.y - mu) * inv * s_lnw[k0+1] + s_lnb[k0+1], 0.f);
                v.z = fmaxf((v.z - mu) * inv * s_lnw[k0+2] + s_lnb[k0+2], 0.f);
                v.w = fmaxf((v.w - mu) * inv * s_lnw[k0+3] + s_lnb[k0+3], 0.f);
                __nv_bfloat162 h01 = __float22bfloat162_rn(make_float2(v.x, v.y));
                __nv_bfloat162 h23 = __float22bfloat162_rn(make_float2(v.z, v.w));
                float2 hf01 = __bfloat1622float2(h01);
                float2 hf23 = __bfloat1622float2(h23);
                __nv_bfloat162 l01 = __float22bfloat162_rn(make_float2(v.x - hf01.x, v.y - hf01.y));
                __nv_bfloat162 l23 = __float22bfloat162_rn(make_float2(v.z - hf23.x, v.w - hf23.y));
                uint32_t off = r * LDA_B + kl * 2;
                *(uint2*)(sm + SM_AHI + off) = make_uint2(*(uint32_t*)&h01, *(uint32_t*)&h23);
                *(uint2*)(sm + SM_ALO + off) = make_uint2(*(uint32_t*)&l01, *(uint32_t*)&l23);
            }
            __syncthreads();

            #pragma unroll
            for (int ks = 0; ks < 4; ++ks) {
                int kk = ks * 16;
                uint32_t Bh[2][4], Bl[2][4];
                {
                    int g  = lane >> 3;
                    int l8 = lane & 7;
                    int brow = kc * 64 + kk + (g & 1) * 8 + l8;
                    #pragma unroll
                    for (int p = 0; p < 2; ++p) {
                        int bcol = 32 * wn + p * 16 + (g >> 1) * 8;
                        uint32_t bo = sb + SM_BHI + brow * LDB_B + bcol * 2;
                        ldsm_x4_t(Bh[p], bo);
                        ldsm_x4_t(Bl[p], bo + (SM_BLO - SM_BHI));
                    }
                }
                #pragma unroll
                for (int mt = 0; mt < 4; ++mt) {
                    uint32_t Ah[4], Al[4];
                    int arow = 64 * wm + 16 * mt + (lane & 15);
                    int acol = kk + 8 * (lane >> 4);
                    uint32_t ao = sb + SM_AHI + arow * LDA_B + acol * 2;
                    ldsm_x4(Ah, ao);
                    ldsm_x4(Al, ao + (SM_ALO - SM_AHI));
                    #pragma unroll
                    for (int p = 0; p < 2; ++p) {
                        mma_bf16(acc[mt][2*p],   Ah, Bh[p]);
                        mma_bf16(acc[mt][2*p+1], Ah, Bh[p] + 2);
                        mma_bf16(acc[mt][2*p],   Ah, Bl[p]);
                        mma_bf16(acc[mt][2*p+1], Ah, Bl[p] + 2);
                        mma_bf16(acc[mt][2*p],   Al, Bh[p]);
                        mma_bf16(acc[mt][2*p+1], Al, Bh[p] + 2);
                    }
                }
            }
        }

        float lsum = 0.f, lsq = 0.f;
        #pragma unroll
        for (int mt = 0; mt < 4; ++mt) {
            #pragma unroll
            for (int nt = 0; nt < 4; ++nt) {
                int r = row0 + 64 * wm + 16 * mt + (lane >> 2);
                int c = 32 * wn + 8 * nt + 2 * (lane & 3);
                float b0 = s_bias[c], b1 = s_bias[c + 1];
                if (r < M) {
                    float2 v = make_float2(acc[mt][nt][0] + b0, acc[mt][nt][1] + b1);
                    lsum += v.x + v.y;
                    lsq  += v.x * v.x + v.y * v.y;
                    *(float2*)(Y + (long long)r * D + c) = v;
                }
                if (r + 8 < M) {
                    float2 v = make_float2(acc[mt][nt][2] + b0, acc[mt][nt][3] + b1);
                    lsum += v.x + v.y;
                    lsq  += v.x * v.x + v.y * v.y;
                    *(float2*)(Y + (long long)(r + 8) * D + c) = v;
                }
            }
        }
        #pragma unroll
        for (int o = 16; o > 0; o >>= 1) {
            lsum += __shfl_down_sync(0xffffffffu, lsum, o);
            lsq  += __shfl_down_sync(0xffffffffu, lsq, o);
        }
        if (lane == 0) {
            atomicAdd(&g_sum[sidx_out],   (double)lsum);
            atomicAdd(&g_sumsq[sidx_out], (double)lsq);
        }
    }
}

// out = relu(graph_layernorm(Y)), sums at index 2.
__global__ void k_apply_out(const float* __restrict__ Y, const float* __restrict__ w,
                            const float* __restrict__ b, float* __restrict__ out) {
    long long i = blockIdx.x * (long long)blockDim.x + threadIdx.x;
    if (i >= NELEM/4) return;
    double m = g_sum[2] * (1.0 / (double)NELEM);
    double v = g_sumsq[2] * (1.0 / (double)NELEM) - m * m;
    if (v < 0.0) v = 0.0;
    float mu  = (float)m;
    float inv = 1.0f / (sqrtf((float)v) + 1e-5f);
    int k = ((int)i * 4) & 127;
    float4 val = __ldg((const float4*)Y + i);
    float4 o;
    o.x = fmaxf((val.x - mu) * inv * __ldg(w + k + 0) + __ldg(b + k + 0), 0.f);
    o.y = fmaxf((val.y - mu) * inv * __ldg(w + k + 1) + __ldg(b + k + 1), 0.f);
    o.z = fmaxf((val.z - mu) * inv * __ldg(w + k + 2) + __ldg(b + k + 2), 0.f);
    o.w = fmaxf((val.w - mu) * inv * __ldg(w + k + 3) + __ldg(b + k + 3), 0.f);
    ((float4*)out)[i] = o;
}

extern "C" void kernel_launch(void* const* d_in, const int* in_sizes, int n_in,
                              void* d_out, int out_size) {
    const float* node = (const float*)d_in[0];
    const int*   ei   = (const int*)d_in[1];
    const float* eps  = (const float*)d_in[4];
    const float* W1   = (const float*)d_in[5];
    const float* b1   = (const float*)d_in[6];
    const float* ln1w = (const float*)d_in[7];
    const float* ln1b = (const float*)d_in[8];
    const float* W2   = (const float*)d_in[9];
    const float* b2   = (const float*)d_in[10];
    const float* ln2w = (const float*)d_in[11];
    const float* ln2b = (const float*)d_in[12];
    const float* W3   = (const float*)d_in[13];
    const float* b3   = (const float*)d_in[14];
    const float* lnow = (const float*)d_in[15];
    const float* lnob = (const float*)d_in[16];

    int E = in_sizes[1] / 2;

    void *p0, *p1, *pw;
    cudaGetSymbolAddress(&p0, g_buf0);
    cudaGetSymbolAddress(&p1, g_buf1);
    cudaGetSymbolAddress(&pw, g_wimg);
    float* buf0 = (float*)p0;
    float* buf1 = (float*)p1;
    __nv_bfloat16* wimg = (__nv_bfloat16*)pw;   // [3][2][16384]

    cudaFuncSetAttribute(k_gemm1,   cudaFuncAttributeMaxDynamicSharedMemorySize, DSMEM1_BYTES);
    cudaFuncSetAttribute(k_gemm_mma, cudaFuncAttributeMaxDynamicSharedMemorySize, DSMEM_BYTES);

    // Weight prep
    k_prepw<<<64, 256>>>(W1, wimg + 0*32768, wimg + 0*32768 + 16384);
    k_prepw<<<64, 256>>>(W2, wimg + 1*32768, wimg + 1*32768 + 16384);
    k_prepw<<<64, 256>>>(W3, wimg + 2*32768, wimg + 2*32768 + 16384);

    // CSR build
    k_zero<<<(NND + 1024) / 1024, 1024>>>();
    k_count<<<(E + 255) / 256, 256>>>(ei, E);
    k_scan1<<<NBLK, 1024>>>();
    k_scan2<<<1, 128>>>();
    k_scan3<<<(NND + 255) / 256, 256>>>(E);
    k_fill<<<(E + 255) / 256, 256>>>(ei, E);

    // Aggregation: h = (1+eps)*node + gather-sum, pre-split to bf16 hi/lo.
    k_aggr<<<(NND * 32 + 255) / 256, 256>>>(node, eps);

    // GEMM layers (persistent)
    k_gemm1<<<GEMM_GRID, 512, DSMEM1_BYTES>>>(wimg + 0*32768, wimg + 0*32768 + 16384,
                                              b1, buf1, NND);
    k_gemm_mma<<<GEMM_GRID, 512, DSMEM_BYTES>>>(buf1, wimg + 1*32768, wimg + 1*32768 + 16384,
                                                b2, ln1w, ln1b, 0, 1, buf0, NND);
    k_gemm_mma<<<GEMM_GRID, 512, DSMEM_BYTES>>>(buf0, wimg + 2*32768, wimg + 2*32768 + 16384,
                                                b3, ln2w, ln2b, 1, 2, buf1, NND);

    int nb_elem = (NELEM/4 + 255) / 256;
    k_apply_out<<<nb_elem, 256>>>(buf1, lnow, lnob, (float*)d_out);
}